// round 1
// baseline (speedup 1.0000x reference)
#include <cuda_runtime.h>
#include <cstdint>

#define NFEAT 784
#define NCLS  10
#define KC    16
#define NTILES 49          // 784 / 16
#define TPB   256
#define ROWS  256
#define XS_STRIDE 20       // 16 + 4 pad: conflict-free & 16B-aligned rows
#define SMEM_FLOATS (NCLS*NFEAT + 2*ROWS*XS_STRIDE)   // 7840 + 10240 = 18080
#define SMEM_BYTES  (SMEM_FLOATS * 4)                 // 72320

__device__ float g_A[NCLS * NFEAT];
__device__ float g_c0[NCLS];

// ---------------------------------------------------------------------------
// Kernel 1: fold the sparse layer + FC into A[10,784], c0[10]
// ---------------------------------------------------------------------------
__global__ void prep_kernel(const float* __restrict__ W,
                            const float* __restrict__ Bsp,
                            const float* __restrict__ fcw,
                            const float* __restrict__ fcb) {
    __shared__ float red[256][NCLS];
    const int tid = threadIdx.x;
    float part[NCLS];
#pragma unroll
    for (int c = 0; c < NCLS; ++c) part[c] = 0.f;

    for (int k = tid; k < NFEAT; k += 256) {
        // scatter column map (faithful to the reference's i=782 wraparound bug)
        int c0i = (k == NFEAT - 2) ? 0 : k;
        int c1i = (k == NFEAT - 2) ? 1 : ((k + 1) % NFEAT);
        float w0 = W[2*k],   w1 = W[2*k+1];
        float b0 = Bsp[2*k], b1 = Bsp[2*k+1];
#pragma unroll
        for (int c = 0; c < NCLS; ++c) {
            float f0 = fcw[c*NFEAT + c0i];
            float f1 = fcw[c*NFEAT + c1i];
            g_A[c*NFEAT + k] = f0*w0 + f1*w1;
            part[c] += f0*b0 + f1*b1;
        }
    }
#pragma unroll
    for (int c = 0; c < NCLS; ++c) red[tid][c] = part[c];
    __syncthreads();
    for (int s = 128; s > 0; s >>= 1) {
        if (tid < s) {
#pragma unroll
            for (int c = 0; c < NCLS; ++c) red[tid][c] += red[tid + s][c];
        }
        __syncthreads();
    }
    if (tid < NCLS) g_c0[tid] = red[0][tid] + fcb[tid];
}

// ---------------------------------------------------------------------------
// cp.async + packed f32x2 FMA helpers
// ---------------------------------------------------------------------------
__device__ __forceinline__ void cp_async16(uint32_t saddr, const void* gptr) {
    asm volatile("cp.async.cg.shared.global [%0], [%1], 16;\n"
                 :: "r"(saddr), "l"(gptr));
}
#define CP_COMMIT() asm volatile("cp.async.commit_group;\n" ::: "memory")
#define CP_WAIT(n)  asm volatile("cp.async.wait_group %0;\n" :: "n"(n) : "memory")
#define FMA_F32X2(d, a, b) \
    asm volatile("fma.rn.f32x2 %0, %1, %2, %0;" : "+l"(d) : "l"(a), "l"(b))

extern __shared__ float smem[];

__device__ __forceinline__ void issue_tile(const float* __restrict__ x,
                                           float* xs, int row0, int Brows,
                                           int tid, int t, int buf) {
    const int k0 = t * KC;
#pragma unroll
    for (int i = 0; i < 4; ++i) {
        int g  = tid + i * TPB;        // 0..1023: (row, 16B-chunk)
        int r  = g >> 2;
        int ch = g & 3;
        int row = row0 + r;
        if (row >= Brows) row = Brows - 1;   // clamp (reads discarded)
        const float* gp = x + (size_t)row * NFEAT + k0 + ch * 4;
        uint32_t sa = (uint32_t)__cvta_generic_to_shared(
            xs + (size_t)buf * ROWS * XS_STRIDE + r * XS_STRIDE + ch * 4);
        cp_async16(sa, gp);
    }
    CP_COMMIT();
}

// ---------------------------------------------------------------------------
// Kernel 2: [B,784] @ A^T + c0, softmax. 1 row/thread, A in shared (broadcast),
// x staged via double-buffered cp.async, packed f32x2 accumulation.
// ---------------------------------------------------------------------------
__global__ void __launch_bounds__(TPB, 3)
main_kernel(const float* __restrict__ x, float* __restrict__ out, int Brows) {
    float* As = smem;                       // [10][784]
    float* xs = smem + NCLS * NFEAT;        // [2][256][20]
    const int tid  = threadIdx.x;
    const int row0 = blockIdx.x * ROWS;

    // stage A into shared (1960 float4 copies, coalesced)
    for (int i = tid; i < (NCLS * NFEAT) / 4; i += TPB)
        ((float4*)As)[i] = ((const float4*)g_A)[i];

    issue_tile(x, xs, row0, Brows, tid, 0, 0);
    issue_tile(x, xs, row0, Brows, tid, 1, 1);
    __syncthreads();   // A visible to all; (cp.async gated by wait_group below)

    unsigned long long acc[NCLS];
#pragma unroll
    for (int c = 0; c < NCLS; ++c) acc[c] = 0ULL;

    const float* xrow = xs + tid * XS_STRIDE;

    for (int t = 0; t < NTILES; ++t) {
        if (t == NTILES - 1) { CP_WAIT(0); } else { CP_WAIT(1); }
        __syncthreads();
        const int buf = t & 1;
        const float* xr = xrow + buf * ROWS * XS_STRIDE;
        const int k0 = t * KC;
#pragma unroll
        for (int kc = 0; kc < 4; ++kc) {
            ulonglong2 xv = *(const ulonglong2*)(xr + kc * 4);
#pragma unroll
            for (int c = 0; c < NCLS; ++c) {
                ulonglong2 av = *(const ulonglong2*)(As + c * NFEAT + k0 + kc * 4);
                FMA_F32X2(acc[c], xv.x, av.x);
                FMA_F32X2(acc[c], xv.y, av.y);
            }
        }
        __syncthreads();
        if (t + 2 < NTILES) issue_tile(x, xs, row0, Brows, tid, t + 2, buf);
    }

    // epilogue: unpack pair-sums, add const, softmax, store
    float logit[NCLS];
#pragma unroll
    for (int c = 0; c < NCLS; ++c) {
        float lo = __uint_as_float((unsigned)(acc[c] & 0xffffffffu));
        float hi = __uint_as_float((unsigned)(acc[c] >> 32));
        logit[c] = lo + hi + g_c0[c];
    }
    float m = logit[0];
#pragma unroll
    for (int c = 1; c < NCLS; ++c) m = fmaxf(m, logit[c]);
    float ssum = 0.f;
#pragma unroll
    for (int c = 0; c < NCLS; ++c) { logit[c] = __expf(logit[c] - m); ssum += logit[c]; }
    float inv = 1.0f / ssum;

    const int row = row0 + tid;
    if (row < Brows) {
#pragma unroll
        for (int c = 0; c < NCLS; ++c)
            out[(size_t)row * NCLS + c] = logit[c] * inv;
    }
}

// ---------------------------------------------------------------------------
extern "C" void kernel_launch(void* const* d_in, const int* in_sizes, int n_in,
                              void* d_out, int out_size) {
    const float* x   = (const float*)d_in[0];
    const float* W   = (const float*)d_in[1];
    const float* bsp = (const float*)d_in[2];
    const float* fcw = (const float*)d_in[3];
    const float* fcb = (const float*)d_in[4];
    float* out = (float*)d_out;
    const int Brows = in_sizes[0] / NFEAT;

    cudaFuncSetAttribute(main_kernel,
                         cudaFuncAttributeMaxDynamicSharedMemorySize, SMEM_BYTES);

    prep_kernel<<<1, 256>>>(W, bsp, fcw, fcb);
    const int grid = (Brows + ROWS - 1) / ROWS;
    main_kernel<<<grid, TPB, SMEM_BYTES>>>(x, out, Brows);
}

// round 2
// speedup vs baseline: 1.3304x; 1.3304x over previous
#include <cuda_runtime.h>
#include <cstdint>

#define NFEAT 784
#define NCLS  10
#define KC    16
#define NT    49           // 784 / 16
#define TPB   128
#define ROWS  128
#define XSTR  20           // 16 + 4 pad: conflict-free LDS.128 & 16B-aligned rows
#define NBUF  3
#define APAD  16           // floats per class per A-tile (10 used)
#define XS_FLOATS (NBUF * ROWS * XSTR)        // 7680
#define AS_FLOATS (NBUF * NCLS * APAD)        // 480
#define SMEM_BYTES ((XS_FLOATS + AS_FLOATS) * 4)   // 32640

__device__ float g_A[NCLS * NFEAT];
__device__ float g_c0[NCLS];

// ---------------------------------------------------------------------------
// Kernel 1: fold sparse layer + FC into A[10,784], c0[10]. 1024 threads, 1 k each.
// ---------------------------------------------------------------------------
__global__ void prep_kernel(const float* __restrict__ W,
                            const float* __restrict__ Bsp,
                            const float* __restrict__ fcw,
                            const float* __restrict__ fcb) {
    __shared__ float red[1024][NCLS];
    const int tid = threadIdx.x;
    float part[NCLS];
#pragma unroll
    for (int c = 0; c < NCLS; ++c) part[c] = 0.f;

    if (tid < NFEAT) {
        const int k = tid;
        // scatter column map (faithful to the reference's i=782 wraparound bug)
        int c0i = (k == NFEAT - 2) ? 0 : k;
        int c1i = (k == NFEAT - 2) ? 1 : ((k + 1) % NFEAT);
        float w0 = W[2*k],   w1 = W[2*k+1];
        float b0 = Bsp[2*k], b1 = Bsp[2*k+1];
#pragma unroll
        for (int c = 0; c < NCLS; ++c) {
            float f0 = fcw[c*NFEAT + c0i];
            float f1 = fcw[c*NFEAT + c1i];
            g_A[c*NFEAT + k] = f0*w0 + f1*w1;
            part[c] = f0*b0 + f1*b1;
        }
    }
#pragma unroll
    for (int c = 0; c < NCLS; ++c) red[tid][c] = part[c];
    __syncthreads();
    for (int s = 512; s > 0; s >>= 1) {
        if (tid < s) {
#pragma unroll
            for (int c = 0; c < NCLS; ++c) red[tid][c] += red[tid + s][c];
        }
        __syncthreads();
    }
    if (tid < NCLS) g_c0[tid] = red[0][tid] + fcb[tid];
}

// ---------------------------------------------------------------------------
// cp.async + packed f32x2 FMA helpers
// ---------------------------------------------------------------------------
__device__ __forceinline__ void cp_async16(uint32_t saddr, const void* gptr) {
    asm volatile("cp.async.cg.shared.global [%0], [%1], 16;\n"
                 :: "r"(saddr), "l"(gptr));
}
#define CP_COMMIT() asm volatile("cp.async.commit_group;\n" ::: "memory")
#define CP_WAIT(n)  asm volatile("cp.async.wait_group %0;\n" :: "n"(n) : "memory")
#define FMA_F32X2(d, a, b) \
    asm volatile("fma.rn.f32x2 %0, %1, %2, %0;" : "+l"(d) : "l"(a), "l"(b))

extern __shared__ float smem[];

// Stage one tile: x[row0..row0+127][k0..k0+15] (coalesced, 4 chunks/thread)
// + A-tile A[0..9][k0..k0+15] (threads 0..39), one cp.async group total.
__device__ __forceinline__ void issue_tile(const float* __restrict__ x,
                                           int row0, int Brows, int tid, int t) {
    const int k0  = t * KC;
    const int buf = t % NBUF;
    float* xb = smem + buf * ROWS * XSTR;
#pragma unroll
    for (int i = 0; i < 4; ++i) {
        int g  = tid + i * TPB;        // 0..511: (row, 16B-chunk)
        int r  = g >> 2;
        int ch = g & 3;
        int row = row0 + r;
        if (row >= Brows) row = Brows - 1;   // clamp (reads discarded)
        const float* gp = x + (size_t)row * NFEAT + k0 + ch * 4;
        uint32_t sa = (uint32_t)__cvta_generic_to_shared(xb + r * XSTR + ch * 4);
        cp_async16(sa, gp);
    }
    if (tid < NCLS * 4) {
        int c  = tid >> 2;
        int ch = tid & 3;
        float* ab = smem + XS_FLOATS + buf * NCLS * APAD;
        uint32_t sa = (uint32_t)__cvta_generic_to_shared(ab + c * APAD + ch * 4);
        cp_async16(sa, g_A + c * NFEAT + k0 + ch * 4);
    }
    CP_COMMIT();
}

// ---------------------------------------------------------------------------
// Kernel 2: [B,784] @ A^T + c0, softmax. 1 row/thread, A streamed in tiles,
// 3-buffer cp.async pipeline with ONE barrier per tile, packed f32x2 FMA.
// ---------------------------------------------------------------------------
__global__ void __launch_bounds__(TPB, 6)
main_kernel(const float* __restrict__ x, float* __restrict__ out, int Brows) {
    const int tid  = threadIdx.x;
    const int row0 = blockIdx.x * ROWS;

    issue_tile(x, row0, Brows, tid, 0);
    issue_tile(x, row0, Brows, tid, 1);

    unsigned long long acc[NCLS];
#pragma unroll
    for (int c = 0; c < NCLS; ++c) acc[c] = 0ULL;

    for (int t = 0; t < NT; ++t) {
        if (t == NT - 1) { CP_WAIT(0); } else { CP_WAIT(1); }
        __syncthreads();          // tile t visible; buf (t+2)%3 fully consumed
        if (t + 2 < NT) issue_tile(x, row0, Brows, tid, t + 2);

        const int buf = t % NBUF;
        const float* xr = smem + buf * ROWS * XSTR + tid * XSTR;
        const float* Ab = smem + XS_FLOATS + buf * NCLS * APAD;
#pragma unroll
        for (int kc = 0; kc < 4; ++kc) {
            ulonglong2 xv = *(const ulonglong2*)(xr + kc * 4);
#pragma unroll
            for (int c = 0; c < NCLS; ++c) {
                ulonglong2 av = *(const ulonglong2*)(Ab + c * APAD + kc * 4);
                FMA_F32X2(acc[c], xv.x, av.x);
                FMA_F32X2(acc[c], xv.y, av.y);
            }
        }
    }

    // epilogue: unpack pair-sums, add const, softmax, store
    float logit[NCLS];
#pragma unroll
    for (int c = 0; c < NCLS; ++c) {
        float lo = __uint_as_float((unsigned)(acc[c] & 0xffffffffu));
        float hi = __uint_as_float((unsigned)(acc[c] >> 32));
        logit[c] = lo + hi + g_c0[c];
    }
    float m = logit[0];
#pragma unroll
    for (int c = 1; c < NCLS; ++c) m = fmaxf(m, logit[c]);
    float ssum = 0.f;
#pragma unroll
    for (int c = 0; c < NCLS; ++c) { logit[c] = __expf(logit[c] - m); ssum += logit[c]; }
    float inv = 1.0f / ssum;

    const int row = row0 + tid;
    if (row < Brows) {
        float2* po = (float2*)(out + (size_t)row * NCLS);
#pragma unroll
        for (int c = 0; c < NCLS; c += 2)
            po[c >> 1] = make_float2(logit[c] * inv, logit[c + 1] * inv);
    }
}

// ---------------------------------------------------------------------------
extern "C" void kernel_launch(void* const* d_in, const int* in_sizes, int n_in,
                              void* d_out, int out_size) {
    const float* x   = (const float*)d_in[0];
    const float* W   = (const float*)d_in[1];
    const float* bsp = (const float*)d_in[2];
    const float* fcw = (const float*)d_in[3];
    const float* fcb = (const float*)d_in[4];
    float* out = (float*)d_out;
    const int Brows = in_sizes[0] / NFEAT;

    prep_kernel<<<1, 1024>>>(W, bsp, fcw, fcb);
    const int grid = (Brows + ROWS - 1) / ROWS;
    main_kernel<<<grid, TPB, SMEM_BYTES>>>(x, out, Brows);
}

// round 3
// speedup vs baseline: 1.6761x; 1.2599x over previous
#include <cuda_runtime.h>
#include <cstdint>

#define NFEAT 784
#define NCLS  10
#define KC    16
#define NT    49                     // 784 / 16
#define TPB   128
#define RPT   2                      // rows per thread
#define ROWS  (TPB * RPT)            // 256 rows per CTA
#define XSTR  20                     // 16 + 4 pad: conflict-free LDS.128
#define NBUF  3
#define XS_FLOATS (NBUF * ROWS * XSTR)   // 15360
#define AS_FLOATS (NCLS * NFEAT)         // 7840
#define RED_FLOATS (4 * NCLS)            // 40
#define SMEM_FLOATS (XS_FLOATS + AS_FLOATS + RED_FLOATS + NCLS + 2)
#define SMEM_BYTES  (SMEM_FLOATS * 4)    // 93008

// ---------------------------------------------------------------------------
__device__ __forceinline__ void cp_async16(uint32_t saddr, const void* gptr) {
    asm volatile("cp.async.cg.shared.global [%0], [%1], 16;\n"
                 :: "r"(saddr), "l"(gptr));
}
#define CP_COMMIT() asm volatile("cp.async.commit_group;\n" ::: "memory")
#define CP_WAIT(n)  asm volatile("cp.async.wait_group %0;\n" :: "n"(n) : "memory")
#define FMA_F32X2(d, a, b) \
    asm volatile("fma.rn.f32x2 %0, %1, %2, %0;" : "+l"(d) : "l"(a), "l"(b))

extern __shared__ float smem[];

// Stage tile t: x[row0 .. row0+255][t*16 .. t*16+15], coalesced, 8 chunks/thread.
__device__ __forceinline__ void issue_tile(const float* __restrict__ x,
                                           int row0, int Brows, int tid, int t) {
    const int k0  = t * KC;
    float* xb = smem + (t % NBUF) * ROWS * XSTR;
#pragma unroll
    for (int i = 0; i < 8; ++i) {
        int g  = tid + i * TPB;        // 0..1023: (row, 16B-chunk)
        int r  = g >> 2;
        int ch = g & 3;
        int row = row0 + r;
        if (row >= Brows) row = Brows - 1;   // clamp (reads discarded)
        const float* gp = x + (size_t)row * NFEAT + k0 + ch * 4;
        uint32_t sa = (uint32_t)__cvta_generic_to_shared(xb + r * XSTR + ch * 4);
        cp_async16(sa, gp);
    }
    CP_COMMIT();
}

// ---------------------------------------------------------------------------
// Single fused kernel: per-CTA fold of sparse+FC into A[10,784] (shared),
// then [256 rows] @ A^T + c0, softmax. 2 rows/thread, 3-buffer cp.async
// pipeline, one barrier per tile, packed f32x2 accumulation.
// ---------------------------------------------------------------------------
__global__ void __launch_bounds__(TPB, 2)
fused_kernel(const float* __restrict__ x,
             const float* __restrict__ W,
             const float* __restrict__ Bsp,
             const float* __restrict__ fcw,
             const float* __restrict__ fcb,
             float* __restrict__ out, int Brows)
{
    float* As  = smem + XS_FLOATS;            // [10][784]
    float* red = As + AS_FLOATS;              // [4][10]
    float* c0s = red + RED_FLOATS;            // [10]

    const int tid  = threadIdx.x;
    const int row0 = blockIdx.x * ROWS;

    // Kick DRAM immediately: prefetch tiles 0 and 1 while we build A.
    issue_tile(x, row0, Brows, tid, 0);
    issue_tile(x, row0, Brows, tid, 1);

    // ---- build A and c0 in shared (replaces the separate prep kernel) ----
    float part[NCLS];
#pragma unroll
    for (int c = 0; c < NCLS; ++c) part[c] = 0.f;

    for (int k = tid; k < NFEAT; k += TPB) {
        // scatter column map (faithful to the reference's i=782 wraparound bug)
        int c0i = (k == NFEAT - 2) ? 0 : k;
        int c1i = (k == NFEAT - 2) ? 1 : ((k + 1 == NFEAT) ? 0 : k + 1);
        float w0 = W[2*k],   w1 = W[2*k+1];
        float b0 = Bsp[2*k], b1 = Bsp[2*k+1];
#pragma unroll
        for (int c = 0; c < NCLS; ++c) {
            float f0 = __ldg(fcw + c * NFEAT + c0i);
            float f1 = __ldg(fcw + c * NFEAT + c1i);
            As[c * NFEAT + k] = f0 * w0 + f1 * w1;
            part[c] += f0 * b0 + f1 * b1;
        }
    }
#pragma unroll
    for (int off = 16; off; off >>= 1)
#pragma unroll
        for (int c = 0; c < NCLS; ++c)
            part[c] += __shfl_down_sync(0xffffffffu, part[c], off);
    if ((tid & 31) == 0)
#pragma unroll
        for (int c = 0; c < NCLS; ++c) red[(tid >> 5) * NCLS + c] = part[c];
    __syncthreads();
    if (tid < NCLS)
        c0s[tid] = red[tid] + red[NCLS + tid] + red[2*NCLS + tid]
                 + red[3*NCLS + tid] + fcb[tid];
    // (ordered before first use by the loop's first __syncthreads)

    // ---- main GEMV loop ----
    unsigned long long acc0[NCLS], acc1[NCLS];
#pragma unroll
    for (int c = 0; c < NCLS; ++c) { acc0[c] = 0ULL; acc1[c] = 0ULL; }

    const float* Aptr = As;
    for (int t = 0; t < NT; ++t) {
        if (t == NT - 1) { CP_WAIT(0); } else { CP_WAIT(1); }
        __syncthreads();          // tile t visible; buf (t+2)%3 fully consumed
        if (t + 2 < NT) issue_tile(x, row0, Brows, tid, t + 2);

        const float* xb  = smem + (t % NBUF) * ROWS * XSTR;
        const float* xr0 = xb + tid * XSTR;
        const float* xr1 = xb + (tid + TPB) * XSTR;
#pragma unroll
        for (int kc = 0; kc < 4; ++kc) {
            ulonglong2 v0 = *(const ulonglong2*)(xr0 + kc * 4);
            ulonglong2 v1 = *(const ulonglong2*)(xr1 + kc * 4);
#pragma unroll
            for (int c = 0; c < NCLS; ++c) {
                ulonglong2 av = *(const ulonglong2*)(Aptr + c * NFEAT + kc * 4);
                FMA_F32X2(acc0[c], v0.x, av.x);
                FMA_F32X2(acc0[c], v0.y, av.y);
                FMA_F32X2(acc1[c], v1.x, av.x);
                FMA_F32X2(acc1[c], v1.y, av.y);
            }
        }
        Aptr += KC;
    }

    // ---- epilogue: unpack pair-sums, + const, softmax, store (2 rows) ----
#pragma unroll
    for (int rsel = 0; rsel < RPT; ++rsel) {
        const unsigned long long* acc = rsel ? acc1 : acc0;
        float logit[NCLS];
#pragma unroll
        for (int c = 0; c < NCLS; ++c) {
            float lo = __uint_as_float((unsigned)(acc[c] & 0xffffffffu));
            float hi = __uint_as_float((unsigned)(acc[c] >> 32));
            logit[c] = lo + hi + c0s[c];
        }
        float m = logit[0];
#pragma unroll
        for (int c = 1; c < NCLS; ++c) m = fmaxf(m, logit[c]);
        float ssum = 0.f;
#pragma unroll
        for (int c = 0; c < NCLS; ++c) { logit[c] = __expf(logit[c] - m); ssum += logit[c]; }
        float inv = 1.0f / ssum;

        const int row = row0 + tid + rsel * TPB;
        if (row < Brows) {
            float2* po = (float2*)(out + (size_t)row * NCLS);
#pragma unroll
            for (int c = 0; c < NCLS; c += 2)
                po[c >> 1] = make_float2(logit[c] * inv, logit[c + 1] * inv);
        }
    }
}

// ---------------------------------------------------------------------------
extern "C" void kernel_launch(void* const* d_in, const int* in_sizes, int n_in,
                              void* d_out, int out_size) {
    const float* x   = (const float*)d_in[0];
    const float* W   = (const float*)d_in[1];
    const float* bsp = (const float*)d_in[2];
    const float* fcw = (const float*)d_in[3];
    const float* fcb = (const float*)d_in[4];
    float* out = (float*)d_out;
    const int Brows = in_sizes[0] / NFEAT;

    cudaFuncSetAttribute(fused_kernel,
                         cudaFuncAttributeMaxDynamicSharedMemorySize, SMEM_BYTES);

    const int grid = (Brows + ROWS - 1) / ROWS;
    fused_kernel<<<grid, TPB, SMEM_BYTES>>>(x, W, bsp, fcw, fcb, out, Brows);
}